// round 3
// baseline (speedup 1.0000x reference)
#include <cuda_runtime.h>

// ---------------------------------------------------------------------------
// LaplacianPyramid, 2-load gather version.
//
// Math: for layer size S sampled at x = u*S - 0.5, breakpoints of floor(x)
// are at u=(k+0.5)/S. For S in {1024,512,256} all breakpoints lie on the
// m/2048 grid, so f2+f3+f4 is exactly piecewise-bilinear on a uniform
// 2048-grid in uv. We precompute its knot values C[2049^2], pack 2x2
// footprints into a float4 table, and keep layer1 (2048; knots at odd/4096)
// in its own footprint table. Gather = 2 scattered LDG.128 per pixel
// (was 4) -> L1tex wavefront count halves.
// ---------------------------------------------------------------------------

__device__ float4 g_P1[2049 * 2049];   // layer1 2x2 footprints (zero-padded)
__device__ float  g_C [2049 * 2049];   // combined f2+f3+f4 knot values
__device__ float4 g_PC[2048 * 2048];   // combined 2x2 footprints

// ---- layer1 footprint pack (zero-padding baked in) ----
__global__ void __launch_bounds__(256) pack1_kernel(const float* __restrict__ src) {
    const int S = 2048;
    int xi = blockIdx.x * blockDim.x + threadIdx.x;  // [0, S]
    int yi = blockIdx.y;                             // [0, S]
    if (xi > S) return;

    int x0 = xi - 1, y0 = yi - 1;
    bool xl = (x0 >= 0), xr = (x0 < S - 1);
    bool yt = (y0 >= 0), yb = (y0 < S - 1);

    float v00 = 0.f, v01 = 0.f, v10 = 0.f, v11 = 0.f;
    if (yt) {
        const float* r = src + (long long)y0 * S;
        if (xl) v00 = r[x0];
        if (xr) v01 = r[x0 + 1];
    }
    if (yb) {
        const float* r = src + (long long)(y0 + 1) * S;
        if (xl) v10 = r[x0];
        if (xr) v11 = r[x0 + 1];
    }
    g_P1[yi * (S + 1) + xi] = make_float4(v00, v01, v10, v11);
}

// ---- evaluate one small layer at knot (m/2048, n/2048), zero padding ----
template <int S>
__device__ __forceinline__ float eval_knot(const float* __restrict__ src, int m, int n) {
    const float inv = (float)S / 2048.0f;  // exact power-of-two scale
    float x = fmaf((float)m, inv, -0.5f);
    float y = fmaf((float)n, inv, -0.5f);
    float xf = floorf(x), yf = floorf(y);
    float wx = x - xf, wy = y - yf;
    int x0 = (int)xf, y0 = (int)yf;

    auto tap = [&](int xx, int yy) -> float {
        if (xx < 0 || xx >= S || yy < 0 || yy >= S) return 0.f;
        return __ldg(src + (long long)yy * S + xx);
    };
    float t00 = tap(x0, y0),     t01 = tap(x0 + 1, y0);
    float t10 = tap(x0, y0 + 1), t11 = tap(x0 + 1, y0 + 1);
    float top = fmaf(wx, t01 - t00, t00);
    float bot = fmaf(wx, t11 - t10, t10);
    return fmaf(wy, bot - top, top);
}

__global__ void __launch_bounds__(256) build_c_kernel(
    const float* __restrict__ l2, const float* __restrict__ l3,
    const float* __restrict__ l4) {
    int m = blockIdx.x * blockDim.x + threadIdx.x;  // [0, 2048]
    int n = blockIdx.y;                             // [0, 2048]
    if (m > 2048) return;
    float v = eval_knot<1024>(l2, m, n) + eval_knot<512>(l3, m, n)
            + eval_knot<256>(l4, m, n);
    g_C[n * 2049 + m] = v;
}

__global__ void __launch_bounds__(256) pack_c_kernel() {
    int m = blockIdx.x * blockDim.x + threadIdx.x;  // [0, 2047]
    int n = blockIdx.y;                             // [0, 2047]
    if (m >= 2048) return;
    const float* r0 = g_C + n * 2049;
    const float* r1 = r0 + 2049;
    g_PC[n * 2048 + m] =
        make_float4(__ldg(r0 + m), __ldg(r0 + m + 1),
                    __ldg(r1 + m), __ldg(r1 + m + 1));
}

// ---- gather: one footprint load for layer1, one for combined f2+f3+f4 ----
__global__ void __launch_bounds__(256) gather_kernel(
    const float2* __restrict__ uv, float* __restrict__ out, int n) {
    int i = blockIdx.x * blockDim.x + threadIdx.x;
    if (i >= n) return;
    float2 g = __ldg(uv + i);
    float u = g.x, v = g.y;

    // layer1: x = u*2048 - 0.5, padded index = floor(x)+1 in [0,2048]
    float x1 = fmaf(u, 2048.f, -0.5f);
    float y1 = fmaf(v, 2048.f, -0.5f);
    float xf1 = floorf(x1), yf1 = floorf(y1);
    int xi1 = max(0, min(2048, (int)xf1 + 1));
    int yi1 = max(0, min(2048, (int)yf1 + 1));

    // combined: knots at u = m/2048, x = u*2048, cell index floor(x) in [0,2047]
    float xc = u * 2048.f;
    float yc = v * 2048.f;
    int xic = min((int)xc, 2047);
    int yic = min((int)yc, 2047);

    // issue both scattered loads back-to-back (MLP=2 + uv already landed)
    float4 t1 = __ldg(g_P1 + yi1 * 2049 + xi1);
    float4 tc = __ldg(g_PC + yic * 2048 + xic);

    float wx1 = x1 - xf1, wy1 = y1 - yf1;
    float top1 = fmaf(wx1, t1.y - t1.x, t1.x);
    float bot1 = fmaf(wx1, t1.w - t1.z, t1.z);
    float a = fmaf(wy1, bot1 - top1, top1);

    float wxc = xc - (float)xic, wyc = yc - (float)yic;
    float topc = fmaf(wxc, tc.y - tc.x, tc.x);
    float botc = fmaf(wxc, tc.w - tc.z, tc.z);
    float b = fmaf(wyc, botc - topc, topc);

    out[i] = a + b;
}

extern "C" void kernel_launch(void* const* d_in, const int* in_sizes, int n_in,
                              void* d_out, int out_size) {
    const float* uv = (const float*)d_in[0];
    const float* l1 = (const float*)d_in[1];  // 2048 x 2048
    const float* l2 = (const float*)d_in[2];  // 1024 x 1024
    const float* l3 = (const float*)d_in[3];  // 512  x 512
    const float* l4 = (const float*)d_in[4];  // 256  x 256

    pack1_kernel<<<dim3((2049 + 255) / 256, 2049), 256>>>(l1);
    build_c_kernel<<<dim3((2049 + 255) / 256, 2049), 256>>>(l2, l3, l4);
    pack_c_kernel<<<dim3(2048 / 256, 2048), 256>>>();

    int n = out_size;  // 8 * 1024 * 1024
    gather_kernel<<<(n + 255) / 256, 256>>>((const float2*)uv, (float*)d_out, n);
}

// round 5
// speedup vs baseline: 1.1806x; 1.1806x over previous
#include <cuda_runtime.h>
#include <cuda_fp16.h>

// ---------------------------------------------------------------------------
// LaplacianPyramid, 2-load gather with fp16 footprint tables.
//
// f2+f3+f4 is exactly piecewise-bilinear on the uniform 2048 uv-grid
// (all floor-breakpoints of the smaller layers lie on m/2048). We precompute
// its knot values C (fp32), then pack 2x2 footprints of C and of layer1 into
// HALF-precision 8-byte entries. Total table set = 67 MB -> fully L2-resident
// (R3's fp32 version was 134 MB and went DRAM-bound at 80% HBM).
// Gather = 2 scattered LDG.64 per pixel, all L2 hits.
// ---------------------------------------------------------------------------

struct alignas(8) H4 {
    __half2 t;  // (v00, v01)  top row
    __half2 b;  // (v10, v11)  bottom row
};

__device__ H4    g_P1h[2049 * 2049];   // layer1 footprints      (33.6 MB)
__device__ H4    g_PCh[2048 * 2048];   // combined footprints    (33.5 MB)
__device__ float g_C  [2049 * 2049];   // combined knots, fp32   (16.8 MB)

// ---- layer1 footprint pack (zero-padding baked in), fp32 -> half4 ----
__global__ void __launch_bounds__(256) pack1_kernel(const float* __restrict__ src) {
    const int S = 2048;
    int xi = blockIdx.x * blockDim.x + threadIdx.x;  // [0, S]
    int yi = blockIdx.y;                             // [0, S]
    if (xi > S) return;

    int x0 = xi - 1, y0 = yi - 1;
    bool xl = (x0 >= 0), xr = (x0 < S - 1);
    bool yt = (y0 >= 0), yb = (y0 < S - 1);

    float v00 = 0.f, v01 = 0.f, v10 = 0.f, v11 = 0.f;
    if (yt) {
        const float* r = src + (long long)y0 * S;
        if (xl) v00 = r[x0];
        if (xr) v01 = r[x0 + 1];
    }
    if (yb) {
        const float* r = src + (long long)(y0 + 1) * S;
        if (xl) v10 = r[x0];
        if (xr) v11 = r[x0 + 1];
    }
    H4 h;
    h.t = __floats2half2_rn(v00, v01);
    h.b = __floats2half2_rn(v10, v11);
    g_P1h[yi * (S + 1) + xi] = h;
}

// ---- evaluate one small layer at knot (m/2048, n/2048), zero padding ----
template <int S>
__device__ __forceinline__ float eval_knot(const float* __restrict__ src, int m, int n) {
    const float sc = (float)S / 2048.0f;  // exact power-of-two scale
    float x = fmaf((float)m, sc, -0.5f);
    float y = fmaf((float)n, sc, -0.5f);
    float xf = floorf(x), yf = floorf(y);
    float wx = x - xf, wy = y - yf;
    int x0 = (int)xf, y0 = (int)yf;

    auto tap = [&](int xx, int yy) -> float {
        if (xx < 0 || xx >= S || yy < 0 || yy >= S) return 0.f;
        return __ldg(src + (long long)yy * S + xx);
    };
    float t00 = tap(x0, y0),     t01 = tap(x0 + 1, y0);
    float t10 = tap(x0, y0 + 1), t11 = tap(x0 + 1, y0 + 1);
    float top = fmaf(wx, t01 - t00, t00);
    float bot = fmaf(wx, t11 - t10, t10);
    return fmaf(wy, bot - top, top);
}

__global__ void __launch_bounds__(256) build_c_kernel(
    const float* __restrict__ l2, const float* __restrict__ l3,
    const float* __restrict__ l4) {
    int m = blockIdx.x * blockDim.x + threadIdx.x;  // [0, 2048]
    int n = blockIdx.y;                             // [0, 2048]
    if (m > 2048) return;
    float v = eval_knot<1024>(l2, m, n) + eval_knot<512>(l3, m, n)
            + eval_knot<256>(l4, m, n);
    g_C[n * 2049 + m] = v;
}

__global__ void __launch_bounds__(256) pack_c_kernel() {
    int m = blockIdx.x * blockDim.x + threadIdx.x;  // [0, 2047]
    int n = blockIdx.y;                             // [0, 2047]
    if (m >= 2048) return;
    const float* r0 = g_C + n * 2049;
    const float* r1 = r0 + 2049;
    H4 h;
    h.t = __floats2half2_rn(__ldg(r0 + m), __ldg(r0 + m + 1));
    h.b = __floats2half2_rn(__ldg(r1 + m), __ldg(r1 + m + 1));
    g_PCh[n * 2048 + m] = h;
}

// ---- per-pixel sample: 2 scattered 8B loads, fp32 lerp math ----
__device__ __forceinline__ float sample_px(float u, float v) {
    // layer1: x = u*2048 - 0.5, padded index = floor(x)+1 in [0,2048]
    float x1 = fmaf(u, 2048.f, -0.5f);
    float y1 = fmaf(v, 2048.f, -0.5f);
    float xf1 = floorf(x1), yf1 = floorf(y1);
    int xi1 = max(0, min(2048, (int)xf1 + 1));
    int yi1 = max(0, min(2048, (int)yf1 + 1));

    // combined surface: cell index floor(u*2048) in [0,2047]
    float xc = u * 2048.f;
    float yc = v * 2048.f;
    int xic = min((int)xc, 2047);
    int yic = min((int)yc, 2047);

    H4 t1 = g_P1h[yi1 * 2049 + xi1];
    H4 tc = g_PCh[yic * 2048 + xic];

    float wx1 = x1 - xf1, wy1 = y1 - yf1;
    float2 a_t = __half22float2(t1.t);
    float2 a_b = __half22float2(t1.b);
    float top1 = fmaf(wx1, a_t.y - a_t.x, a_t.x);
    float bot1 = fmaf(wx1, a_b.y - a_b.x, a_b.x);
    float a = fmaf(wy1, bot1 - top1, top1);

    float wxc = xc - (float)xic, wyc = yc - (float)yic;
    float2 c_t = __half22float2(tc.t);
    float2 c_b = __half22float2(tc.b);
    float topc = fmaf(wxc, c_t.y - c_t.x, c_t.x);
    float botc = fmaf(wxc, c_b.y - c_b.x, c_b.x);
    float b = fmaf(wyc, botc - topc, topc);

    return a + b;
}

// 2 pixels per thread: float4 uv load, float2 out store, MLP=4 scattered loads.
__global__ void __launch_bounds__(256) gather_kernel(
    const float4* __restrict__ uv2, float2* __restrict__ out2, int npair) {
    int i = blockIdx.x * blockDim.x + threadIdx.x;
    if (i >= npair) return;
    float4 g = __ldg(uv2 + i);
    float r0 = sample_px(g.x, g.y);
    float r1 = sample_px(g.z, g.w);
    out2[i] = make_float2(r0, r1);
}

extern "C" void kernel_launch(void* const* d_in, const int* in_sizes, int n_in,
                              void* d_out, int out_size) {
    const float* uv = (const float*)d_in[0];
    const float* l1 = (const float*)d_in[1];  // 2048 x 2048
    const float* l2 = (const float*)d_in[2];  // 1024 x 1024
    const float* l3 = (const float*)d_in[3];  // 512  x 512
    const float* l4 = (const float*)d_in[4];  // 256  x 256

    pack1_kernel<<<dim3((2049 + 255) / 256, 2049), 256>>>(l1);
    build_c_kernel<<<dim3((2049 + 255) / 256, 2049), 256>>>(l2, l3, l4);
    pack_c_kernel<<<dim3(2048 / 256, 2048), 256>>>();

    int npair = out_size / 2;  // 8*1024*1024 / 2
    gather_kernel<<<(npair + 255) / 256, 256>>>(
        (const float4*)uv, (float2*)d_out, npair);
}

// round 6
// speedup vs baseline: 1.6348x; 1.3847x over previous
#include <cuda_runtime.h>
#include <cuda_fp16.h>

// ---------------------------------------------------------------------------
// LaplacianPyramid. Gather = 2 scattered LDG.64/pixel from fp16 footprint
// tables (67 MB, L2-resident) — at the L1tex wavefront floor (~110us).
// This round: cheap pack phase via separable resampling + vectorized packs,
// and streaming cache hints on uv/out so they stop evicting the tables.
// ---------------------------------------------------------------------------

struct alignas(8) H4 {
    __half2 t;  // (v00, v01)
    __half2 b;  // (v10, v11)
};

__device__ H4    g_P1h[2049 * 2049];   // layer1 footprints      (33.6 MB)
__device__ H4    g_PCh[2048 * 2048];   // combined footprints    (33.5 MB)
__device__ float g_C  [2049 * 2049];   // combined knots, fp32   (16.8 MB)
__device__ float g_H2 [1024 * 2049];   // horizontal pass, S=1024
__device__ float g_H3 [ 512 * 2049];   // S=512
__device__ float g_H4 [ 256 * 2049];   // S=256

template <int S>
__device__ __forceinline__ float* hbuf() {
    if constexpr (S == 1024) return g_H2;
    else if constexpr (S == 512) return g_H3;
    else return g_H4;
}

// ---- layer1 footprint pack, 4 entries/thread ----
__global__ void __launch_bounds__(256) pack1_kernel(const float* __restrict__ src) {
    const int S = 2048;
    int x4 = (blockIdx.x * blockDim.x + threadIdx.x) * 4;  // base xi
    int yi = blockIdx.y;                                   // [0, S]
    if (x4 > S) return;

    int y0 = yi - 1;
    bool yt = (y0 >= 0);
    bool yb = (y0 < S - 1);
    const float* r0 = src + (long long)y0 * S;
    const float* r1 = r0 + S;

    float a[5], b[5];
#pragma unroll
    for (int k = 0; k < 5; k++) {
        int c = x4 - 1 + k;
        bool cv = (c >= 0) & (c < S);
        a[k] = (yt && cv) ? __ldg(r0 + c) : 0.f;
        b[k] = (yb && cv) ? __ldg(r1 + c) : 0.f;
    }
    H4* dst = g_P1h + yi * (S + 1) + x4;
#pragma unroll
    for (int k = 0; k < 4; k++) {
        if (x4 + k <= S) {
            H4 h;
            h.t = __floats2half2_rn(a[k], a[k + 1]);
            h.b = __floats2half2_rn(b[k], b[k + 1]);
            dst[k] = h;
        }
    }
}

// ---- horizontal resample of layer S onto the 2048-knot x-grid ----
template <int S>
__global__ void __launch_bounds__(256) hpass_kernel(const float* __restrict__ src) {
    int m = blockIdx.x * blockDim.x + threadIdx.x;  // [0, 2048]
    int y = blockIdx.y;                             // [0, S)
    if (m > 2048) return;
    const float sc = (float)S / 2048.0f;
    float x = fmaf((float)m, sc, -0.5f);
    float xf = floorf(x);
    float wx = x - xf;
    int x0 = (int)xf;
    const float* r = src + (long long)y * S;
    float v0 = (x0 >= 0 && x0 < S) ? __ldg(r + x0) : 0.f;
    float v1 = (x0 + 1 >= 0 && x0 + 1 < S) ? __ldg(r + x0 + 1) : 0.f;
    hbuf<S>()[y * 2049 + m] = fmaf(wx, v1 - v0, v0);
}

// ---- vertical resample + sum over layers -> C knots ----
template <int S>
__device__ __forceinline__ float vtap(int m, int n) {
    const float sc = (float)S / 2048.0f;
    float y = fmaf((float)n, sc, -0.5f);
    float yf = floorf(y);
    float wy = y - yf;
    int y0 = (int)yf;
    const float* H = hbuf<S>();
    float v0 = (y0 >= 0 && y0 < S) ? __ldg(H + y0 * 2049 + m) : 0.f;
    float v1 = (y0 + 1 >= 0 && y0 + 1 < S) ? __ldg(H + (y0 + 1) * 2049 + m) : 0.f;
    return fmaf(wy, v1 - v0, v0);
}

__global__ void __launch_bounds__(256) vpass_kernel() {
    int m = blockIdx.x * blockDim.x + threadIdx.x;  // [0, 2048]
    int n = blockIdx.y;                             // [0, 2048]
    if (m > 2048) return;
    g_C[n * 2049 + m] = vtap<1024>(m, n) + vtap<512>(m, n) + vtap<256>(m, n);
}

// ---- combined footprint pack, 4 entries/thread, 16B vector stores ----
__global__ void __launch_bounds__(256) pack_c_kernel() {
    int m4 = (blockIdx.x * blockDim.x + threadIdx.x) * 4;  // [0, 2044], full
    int n = blockIdx.y;                                    // [0, 2047]
    if (m4 >= 2048) return;
    const float* r0 = g_C + n * 2049 + m4;
    const float* r1 = r0 + 2049;
    float a[5], b[5];
#pragma unroll
    for (int k = 0; k < 5; k++) {
        a[k] = __ldg(r0 + k);
        b[k] = __ldg(r1 + k);
    }
    H4 e[4];
#pragma unroll
    for (int k = 0; k < 4; k++) {
        e[k].t = __floats2half2_rn(a[k], a[k + 1]);
        e[k].b = __floats2half2_rn(b[k], b[k + 1]);
    }
    // entries are 32B-aligned (m4 % 4 == 0, stride 2048): two 16B stores
    float4* dst = reinterpret_cast<float4*>(g_PCh + n * 2048 + m4);
    dst[0] = *reinterpret_cast<float4*>(&e[0]);
    dst[1] = *reinterpret_cast<float4*>(&e[2]);
}

// ---- per-pixel sample: 2 scattered 8B loads, fp32 lerp math ----
__device__ __forceinline__ float sample_px(float u, float v) {
    float x1 = fmaf(u, 2048.f, -0.5f);
    float y1 = fmaf(v, 2048.f, -0.5f);
    float xf1 = floorf(x1), yf1 = floorf(y1);
    int xi1 = max(0, min(2048, (int)xf1 + 1));
    int yi1 = max(0, min(2048, (int)yf1 + 1));

    float xc = u * 2048.f;
    float yc = v * 2048.f;
    int xic = min((int)xc, 2047);
    int yic = min((int)yc, 2047);

    H4 t1 = g_P1h[yi1 * 2049 + xi1];
    H4 tc = g_PCh[yic * 2048 + xic];

    float wx1 = x1 - xf1, wy1 = y1 - yf1;
    float2 a_t = __half22float2(t1.t);
    float2 a_b = __half22float2(t1.b);
    float top1 = fmaf(wx1, a_t.y - a_t.x, a_t.x);
    float bot1 = fmaf(wx1, a_b.y - a_b.x, a_b.x);
    float a = fmaf(wy1, bot1 - top1, top1);

    float wxc = xc - (float)xic, wyc = yc - (float)yic;
    float2 c_t = __half22float2(tc.t);
    float2 c_b = __half22float2(tc.b);
    float topc = fmaf(wxc, c_t.y - c_t.x, c_t.x);
    float botc = fmaf(wxc, c_b.y - c_b.x, c_b.x);
    float b = fmaf(wyc, botc - topc, topc);

    return a + b;
}

// 2 pixels/thread. uv/out use streaming (evict-first) hints so they don't
// evict the 67 MB table set from L2.
__global__ void __launch_bounds__(256) gather_kernel(
    const float4* __restrict__ uv2, float2* __restrict__ out2, int npair) {
    int i = blockIdx.x * blockDim.x + threadIdx.x;
    if (i >= npair) return;
    float4 g = __ldcs(uv2 + i);
    float r0 = sample_px(g.x, g.y);
    float r1 = sample_px(g.z, g.w);
    __stcs(out2 + i, make_float2(r0, r1));
}

extern "C" void kernel_launch(void* const* d_in, const int* in_sizes, int n_in,
                              void* d_out, int out_size) {
    const float* uv = (const float*)d_in[0];
    const float* l1 = (const float*)d_in[1];  // 2048 x 2048
    const float* l2 = (const float*)d_in[2];  // 1024 x 1024
    const float* l3 = (const float*)d_in[3];  // 512  x 512
    const float* l4 = (const float*)d_in[4];  // 256  x 256

    dim3 row9((2049 + 255) / 256, 0, 1);

    hpass_kernel<1024><<<dim3(9, 1024), 256>>>(l2);
    hpass_kernel<512><<<dim3(9, 512), 256>>>(l3);
    hpass_kernel<256><<<dim3(9, 256), 256>>>(l4);
    pack1_kernel<<<dim3((513 + 255) / 256, 2049), 256>>>(l1);   // 513 thr/row
    vpass_kernel<<<dim3(9, 2049), 256>>>();
    pack_c_kernel<<<dim3(2, 2048), 256>>>();                    // 512 thr/row

    int npair = out_size / 2;  // 8*1024*1024 / 2
    gather_kernel<<<(npair + 255) / 256, 256>>>(
        (const float4*)uv, (float2*)d_out, npair);
}